// round 4
// baseline (speedup 1.0000x reference)
#include <cuda_runtime.h>

#define BATCH 8
#define HH 1024
#define WW 1024

#define TILE 104          // valid output span per tile dim
#define HALO 12           // >= 10 needed; 12 keeps float4 alignment
#define EXT  128          // TILE + 2*HALO
#define NWARP 32
#define RPW  4            // rows per warp (NWARP*RPW == EXT)
#define NT   1024
#define NITER 10

#define SMEM_BYTES ((2*EXT*EXT + 2*NWARP*EXT) * 4)

__device__ __forceinline__ float sigm(float x) {
    return __fdividef(1.0f, 1.0f + __expf(-x));
}

__global__ void __launch_bounds__(NT, 1)
ccs_fused(const float* __restrict__ o, const float* __restrict__ vf,
          float* __restrict__ out) {
    extern __shared__ float sm[];
    float* sv0 = sm;                    // vf0 [EXT][EXT] (zeroed outside image)
    float* sv1 = sm + EXT * EXT;        // vf1 [EXT][EXT]
    float* xu  = sm + 2 * EXT * EXT;    // per-warp u top-row exchange [NWARP][EXT]
    float* xq  = xu + NWARP * EXT;      // per-warp q bottom-row exchange

    const int tid  = threadIdx.x;
    const int w    = tid >> 5;
    const int lane = tid & 31;
    const int tx = blockIdx.x, ty = blockIdx.y, b = blockIdx.z;
    const int gi0 = ty * TILE - HALO;
    const int gj0 = tx * TILE - HALO;            // multiple of 4
    const int colbase = gj0 + lane * 4;          // global col of this lane's elem 0
    const int cb = min(max(colbase, 0), WW - 4); // clamped, stays 16B aligned

    // column in-image mask (constant over rows)
    float4 cm;
    cm.x = ((unsigned)(colbase + 0) < WW) ? 1.f : 0.f;
    cm.y = ((unsigned)(colbase + 1) < WW) ? 1.f : 0.f;
    cm.z = ((unsigned)(colbase + 2) < WW) ? 1.f : 0.f;
    cm.w = ((unsigned)(colbase + 3) < WW) ? 1.f : 0.f;

    // ---- load vector field into smem, deinterleave, zero out-of-image ----
    for (int k = tid; k < EXT * EXT / 2; k += NT) {
        int er = k >> 6;              // 64 px-pairs per 128-col row
        int ec = (k & 63) << 1;
        int gr = gi0 + er;
        int gc = gj0 + ec;
        int grc = min(max(gr, 0), HH - 1);
        int gcc = min(max(gc, 0), WW - 2);
        float4 v = *reinterpret_cast<const float4*>(vf + ((size_t)grc * WW + gcc) * 2);
        float mr = ((unsigned)gr < HH) ? 1.f : 0.f;
        float m0 = mr * (((unsigned)gc < WW) ? 1.f : 0.f);
        float m1 = mr * (((unsigned)(gc + 1) < WW) ? 1.f : 0.f);
        sv0[er * EXT + ec]     = v.x * m0;  sv1[er * EXT + ec]     = v.y * m0;
        sv0[er * EXT + ec + 1] = v.z * m1;  sv1[er * EXT + ec + 1] = v.w * m1;
    }

    // ---- init: u = sigmoid(2*o), q = 0 (register resident) ----
    const float* ob = o + (size_t)b * HH * WW;
    float4 u[RPW], q[RPW];
#pragma unroll
    for (int r = 0; r < RPW; r++) {
        int er = w * RPW + r;
        int gr = gi0 + er;
        int grc = min(max(gr, 0), HH - 1);
        float4 o4 = *reinterpret_cast<const float4*>(ob + (size_t)grc * WW + cb);
        float rm = ((unsigned)gr < HH) ? 1.f : 0.f;
        u[r].x = cm.x * rm * sigm(2.f * o4.x);
        u[r].y = cm.y * rm * sigm(2.f * o4.y);
        u[r].z = cm.z * rm * sigm(2.f * o4.z);
        u[r].w = cm.w * rm * sigm(2.f * o4.w);
        q[r] = make_float4(0.f, 0.f, 0.f, 0.f);
    }
    *reinterpret_cast<float4*>(&xu[w * EXT + lane * 4]) = u[0];
    __syncthreads();

    for (int it = 0; it < NITER; it++) {
        const bool last = (it == NITER - 1);

        // ===== q-step: q = max(q - 0.5*((u_dn-u)*vf1 + (u_rt-u)*vf0), 0) =====
        // out-of-image cells: vf==0 in smem -> q stays exactly 0 (no mask needed)
#pragma unroll
        for (int r = 0; r < RPW; r++) {
            int er = w * RPW + r;
            float4 ud;
            if (r < RPW - 1)          ud = u[r + 1];
            else if (w < NWARP - 1)   ud = *reinterpret_cast<float4*>(&xu[(w + 1) * EXT + lane * 4]);
            else                      ud = make_float4(0.f, 0.f, 0.f, 0.f);
            float ur = __shfl_down_sync(0xffffffffu, u[r].x, 1);
            if (lane == 31) ur = 0.f;
            float4 v0 = *reinterpret_cast<float4*>(&sv0[er * EXT + lane * 4]);
            float4 v1 = *reinterpret_cast<float4*>(&sv1[er * EXT + lane * 4]);
            float t;
            t = (ud.x - u[r].x) * v1.x + (u[r].y - u[r].x) * v0.x;
            q[r].x = fmaxf(fmaf(-0.5f, t, q[r].x), 0.f);
            t = (ud.y - u[r].y) * v1.y + (u[r].z - u[r].y) * v0.y;
            q[r].y = fmaxf(fmaf(-0.5f, t, q[r].y), 0.f);
            t = (ud.z - u[r].z) * v1.z + (u[r].w - u[r].z) * v0.z;
            q[r].z = fmaxf(fmaf(-0.5f, t, q[r].z), 0.f);
            t = (ud.w - u[r].w) * v1.w + (ur - u[r].w) * v0.w;
            q[r].w = fmaxf(fmaf(-0.5f, t, q[r].w), 0.f);
        }
        *reinterpret_cast<float4*>(&xq[w * EXT + lane * 4]) = q[RPW - 1];
        __syncthreads();

        // ===== u-step: Tq = div(vf*q); u = sigmoid(2*(o - Tq)) (or final out) =====
        {
            int er0 = w * RPW;
            float4 v1p = *reinterpret_cast<float4*>(&sv1[max(er0 - 1, 0) * EXT + lane * 4]);
            float4 qup;
            if (w > 0) qup = *reinterpret_cast<float4*>(&xq[(w - 1) * EXT + lane * 4]);
            else       qup = make_float4(0.f, 0.f, 0.f, 0.f);
#pragma unroll
            for (int r = 0; r < RPW; r++) {
                int er = er0 + r;
                int gr = gi0 + er;
                int grc = min(max(gr, 0), HH - 1);
                float4 v1 = *reinterpret_cast<float4*>(&sv1[er * EXT + lane * 4]);
                float4 v0 = *reinterpret_cast<float4*>(&sv0[er * EXT + lane * 4]);
                float v0l = __shfl_up_sync(0xffffffffu, v0.w, 1);
                float ql  = __shfl_up_sync(0xffffffffu, q[r].w, 1);
                if (lane == 0) { v0l = 0.f; ql = 0.f; }
                float4 o4 = *reinterpret_cast<const float4*>(ob + (size_t)grc * WW + cb);

                float Tq0 = v1.x * q[r].x - v1p.x * qup.x + v0.x * q[r].x - v0l  * ql;
                float Tq1 = v1.y * q[r].y - v1p.y * qup.y + v0.y * q[r].y - v0.x * q[r].x;
                float Tq2 = v1.z * q[r].z - v1p.z * qup.z + v0.z * q[r].z - v0.y * q[r].y;
                float Tq3 = v1.w * q[r].w - v1p.w * qup.w + v0.w * q[r].w - v0.z * q[r].z;
                float x0 = 2.f * (o4.x - Tq0);
                float x1 = 2.f * (o4.y - Tq1);
                float x2 = 2.f * (o4.z - Tq2);
                float x3 = 2.f * (o4.w - Tq3);

                if (!last) {
                    float rm = ((unsigned)gr < HH) ? 1.f : 0.f;
                    u[r].x = cm.x * rm * sigm(x0);
                    u[r].y = cm.y * rm * sigm(x1);
                    u[r].z = cm.z * rm * sigm(x2);
                    u[r].w = cm.w * rm * sigm(x3);
                } else {
                    // final: out = (o - Tq)/EPS, only the tile's valid center
                    if (er >= HALO && er < HALO + TILE && gr < HH &&
                        lane >= HALO / 4 && lane < (HALO + TILE) / 4 && colbase < WW) {
                        *reinterpret_cast<float4*>(out + (size_t)((b * HH + gr) * WW + colbase)) =
                            make_float4(x0, x1, x2, x3);
                    }
                }
                v1p = v1;
                qup = q[r];
            }
        }
        if (!last) {
            *reinterpret_cast<float4*>(&xu[w * EXT + lane * 4]) = u[0];
        }
        __syncthreads();
    }
}

extern "C" void kernel_launch(void* const* d_in, const int* in_sizes, int n_in,
                              void* d_out, int out_size) {
    const float* o  = (const float*)d_in[0];
    const float* vf = (const float*)d_in[1];
    float* out = (float*)d_out;

    static bool attr_set = false;
    if (!attr_set) {
        cudaFuncSetAttribute(ccs_fused, cudaFuncAttributeMaxDynamicSharedMemorySize,
                             SMEM_BYTES);
        attr_set = true;
    }

    dim3 grid((WW + TILE - 1) / TILE, (HH + TILE - 1) / TILE, BATCH);  // 10 x 10 x 8
    ccs_fused<<<grid, NT, SMEM_BYTES>>>(o, vf, out);
}

// round 5
// speedup vs baseline: 1.3598x; 1.3598x over previous
#include <cuda_runtime.h>

#define BATCH 8
#define HH 1024
#define WW 1024

#define TILE 104          // valid output span per tile dim
#define HALO 12           // >= 10 needed; 12 keeps float4 alignment
#define EXT  128          // TILE + 2*HALO
#define NWARP 16
#define RPW  8            // rows per warp (NWARP*RPW == EXT)
#define NT   512
#define NITER 10

#define SMEM_BYTES ((2*EXT*EXT + 2*NWARP*EXT) * 4)

// sigmoid(2x) = 0.5*tanh(x) + 0.5  -> one MUFU instead of EX2+RCP
__device__ __forceinline__ float tanh_fast(float x) {
    float y;
    asm("tanh.approx.f32 %0, %1;" : "=f"(y) : "f"(x));
    return y;
}

__global__ void __launch_bounds__(NT, 1)
ccs_fused(const float* __restrict__ o, const float* __restrict__ vf,
          float* __restrict__ out) {
    extern __shared__ float sm[];
    float* sv0 = sm;                    // vf0 [EXT][EXT] (zeroed outside image)
    float* sv1 = sm + EXT * EXT;        // vf1 [EXT][EXT]
    float* xu  = sm + 2 * EXT * EXT;    // per-warp u top-row exchange [NWARP][EXT]
    float* xq  = xu + NWARP * EXT;      // per-warp q bottom-row exchange

    const int tid  = threadIdx.x;
    const int w    = tid >> 5;
    const int lane = tid & 31;
    const int tx = blockIdx.x, ty = blockIdx.y, b = blockIdx.z;
    const int gi0 = ty * TILE - HALO;
    const int gj0 = tx * TILE - HALO;            // multiple of 4
    const int colbase = gj0 + lane * 4;          // global col of this lane's elem 0
    const int cb = min(max(colbase, 0), WW - 4); // clamped, stays 16B aligned

    // column in-image mask (constant over rows)
    float4 cm;
    cm.x = ((unsigned)(colbase + 0) < WW) ? 1.f : 0.f;
    cm.y = ((unsigned)(colbase + 1) < WW) ? 1.f : 0.f;
    cm.z = ((unsigned)(colbase + 2) < WW) ? 1.f : 0.f;
    cm.w = ((unsigned)(colbase + 3) < WW) ? 1.f : 0.f;

    // ---- load vector field into smem, deinterleave, zero out-of-image ----
    for (int k = tid; k < EXT * EXT / 2; k += NT) {
        int er = k >> 6;              // 64 px-pairs per 128-col row
        int ec = (k & 63) << 1;
        int gr = gi0 + er;
        int gc = gj0 + ec;
        int grc = min(max(gr, 0), HH - 1);
        int gcc = min(max(gc, 0), WW - 2);
        float4 v = *reinterpret_cast<const float4*>(vf + ((size_t)grc * WW + gcc) * 2);
        float mr = ((unsigned)gr < HH) ? 1.f : 0.f;
        float m0 = mr * (((unsigned)gc < WW) ? 1.f : 0.f);
        float m1 = mr * (((unsigned)(gc + 1) < WW) ? 1.f : 0.f);
        sv0[er * EXT + ec]     = v.x * m0;  sv1[er * EXT + ec]     = v.y * m0;
        sv0[er * EXT + ec + 1] = v.z * m1;  sv1[er * EXT + ec + 1] = v.w * m1;
    }

    // ---- init: u = sigmoid(2*o) = 0.5*tanh(o)+0.5, q = 0 (register resident) ----
    const float* ob = o + (size_t)b * HH * WW;
    float4 u[RPW], q[RPW];
#pragma unroll
    for (int r = 0; r < RPW; r++) {
        int er = w * RPW + r;
        int gr = gi0 + er;
        int grc = min(max(gr, 0), HH - 1);
        float4 o4 = *reinterpret_cast<const float4*>(ob + (size_t)grc * WW + cb);
        float rm = ((unsigned)gr < HH) ? 1.f : 0.f;
        u[r].x = (cm.x * rm) * fmaf(tanh_fast(o4.x), 0.5f, 0.5f);
        u[r].y = (cm.y * rm) * fmaf(tanh_fast(o4.y), 0.5f, 0.5f);
        u[r].z = (cm.z * rm) * fmaf(tanh_fast(o4.z), 0.5f, 0.5f);
        u[r].w = (cm.w * rm) * fmaf(tanh_fast(o4.w), 0.5f, 0.5f);
        q[r] = make_float4(0.f, 0.f, 0.f, 0.f);
    }
    *reinterpret_cast<float4*>(&xu[w * EXT + lane * 4]) = u[0];
    __syncthreads();

    // ---- iteration-invariant left-neighbor vf0 per row (replaces a shfl in the loop) ----
    float v0l[RPW];
#pragma unroll
    for (int r = 0; r < RPW; r++) {
        int er = w * RPW + r;
        v0l[r] = (lane > 0) ? sv0[er * EXT + lane * 4 - 1] : 0.f;
    }

#pragma unroll 1
    for (int it = 0; it < NITER; it++) {
        const bool last = (it == NITER - 1);

        // ===== q-step: q = max(q - 0.5*((u_dn-u)*vf1 + (u_rt-u)*vf0), 0) =====
        // out-of-image cells: vf==0 in smem -> q stays exactly 0 (no mask needed)
#pragma unroll
        for (int r = 0; r < RPW; r++) {
            int er = w * RPW + r;
            float4 ud;
            if (r < RPW - 1)          ud = u[r + 1];
            else if (w < NWARP - 1)   ud = *reinterpret_cast<float4*>(&xu[(w + 1) * EXT + lane * 4]);
            else                      ud = make_float4(0.f, 0.f, 0.f, 0.f);
            float ur = __shfl_down_sync(0xffffffffu, u[r].x, 1);
            if (lane == 31) ur = 0.f;
            float4 v0 = *reinterpret_cast<float4*>(&sv0[er * EXT + lane * 4]);
            float4 v1 = *reinterpret_cast<float4*>(&sv1[er * EXT + lane * 4]);
            float t;
            t = (ud.x - u[r].x) * v1.x + (u[r].y - u[r].x) * v0.x;
            q[r].x = fmaxf(fmaf(-0.5f, t, q[r].x), 0.f);
            t = (ud.y - u[r].y) * v1.y + (u[r].z - u[r].y) * v0.y;
            q[r].y = fmaxf(fmaf(-0.5f, t, q[r].y), 0.f);
            t = (ud.z - u[r].z) * v1.z + (u[r].w - u[r].z) * v0.z;
            q[r].z = fmaxf(fmaf(-0.5f, t, q[r].z), 0.f);
            t = (ud.w - u[r].w) * v1.w + (ur - u[r].w) * v0.w;
            q[r].w = fmaxf(fmaf(-0.5f, t, q[r].w), 0.f);
        }
        *reinterpret_cast<float4*>(&xq[w * EXT + lane * 4]) = q[RPW - 1];
        __syncthreads();

        // ===== u-step: Tq = div(vf*q); x = o - Tq; u = 0.5*tanh(x)+0.5 (or out = 2x) =====
        {
            int er0 = w * RPW;
            float4 v1p = *reinterpret_cast<float4*>(&sv1[max(er0 - 1, 0) * EXT + lane * 4]);
            float4 qup;
            if (w > 0) qup = *reinterpret_cast<float4*>(&xq[(w - 1) * EXT + lane * 4]);
            else       qup = make_float4(0.f, 0.f, 0.f, 0.f);
#pragma unroll
            for (int r = 0; r < RPW; r++) {
                int er = er0 + r;
                int gr = gi0 + er;
                int grc = min(max(gr, 0), HH - 1);
                float4 v1 = *reinterpret_cast<float4*>(&sv1[er * EXT + lane * 4]);
                float4 v0 = *reinterpret_cast<float4*>(&sv0[er * EXT + lane * 4]);
                float ql = __shfl_up_sync(0xffffffffu, q[r].w, 1);
                if (lane == 0) ql = 0.f;
                float4 o4 = *reinterpret_cast<const float4*>(ob + (size_t)grc * WW + cb);

                float Tq0 = v1.x * q[r].x - v1p.x * qup.x + v0.x * q[r].x - v0l[r] * ql;
                float Tq1 = v1.y * q[r].y - v1p.y * qup.y + v0.y * q[r].y - v0.x * q[r].x;
                float Tq2 = v1.z * q[r].z - v1p.z * qup.z + v0.z * q[r].z - v0.y * q[r].y;
                float Tq3 = v1.w * q[r].w - v1p.w * qup.w + v0.w * q[r].w - v0.z * q[r].z;
                float x0 = o4.x - Tq0;
                float x1 = o4.y - Tq1;
                float x2 = o4.z - Tq2;
                float x3 = o4.w - Tq3;

                if (!last) {
                    float rm = ((unsigned)gr < HH) ? 1.f : 0.f;
                    u[r].x = (cm.x * rm) * fmaf(tanh_fast(x0), 0.5f, 0.5f);
                    u[r].y = (cm.y * rm) * fmaf(tanh_fast(x1), 0.5f, 0.5f);
                    u[r].z = (cm.z * rm) * fmaf(tanh_fast(x2), 0.5f, 0.5f);
                    u[r].w = (cm.w * rm) * fmaf(tanh_fast(x3), 0.5f, 0.5f);
                } else {
                    // final: out = (o - Tq)/EPS = 2*x, only the tile's valid center
                    if (er >= HALO && er < HALO + TILE && gr < HH &&
                        lane >= HALO / 4 && lane < (HALO + TILE) / 4 && colbase < WW) {
                        *reinterpret_cast<float4*>(out + (size_t)((b * HH + gr) * WW + colbase)) =
                            make_float4(2.f * x0, 2.f * x1, 2.f * x2, 2.f * x3);
                    }
                }
                v1p = v1;
                qup = q[r];
            }
        }
        if (!last) {
            *reinterpret_cast<float4*>(&xu[w * EXT + lane * 4]) = u[0];
        }
        __syncthreads();
    }
}

extern "C" void kernel_launch(void* const* d_in, const int* in_sizes, int n_in,
                              void* d_out, int out_size) {
    const float* o  = (const float*)d_in[0];
    const float* vf = (const float*)d_in[1];
    float* out = (float*)d_out;

    static bool attr_set = false;
    if (!attr_set) {
        cudaFuncSetAttribute(ccs_fused, cudaFuncAttributeMaxDynamicSharedMemorySize,
                             SMEM_BYTES);
        attr_set = true;
    }

    dim3 grid((WW + TILE - 1) / TILE, (HH + TILE - 1) / TILE, BATCH);  // 10 x 10 x 8
    ccs_fused<<<grid, NT, SMEM_BYTES>>>(o, vf, out);
}